// round 9
// baseline (speedup 1.0000x reference)
#include <cuda_runtime.h>
#include <cstdint>

// IF neuron multi-step scan, hard reset:
//   h_t = x_t + v_{t-1};  s_t = (h_t >= 1) ? 1 : 0;  v_t = s_t ? 0 : h_t
//
// R9: 256-bit global accesses (ld/st .v8.b32 — legal on sm_103a, and the
// only width where inline L2::evict_* modifiers are accepted). One thread
// owns 8 contiguous floats; batch-4 bursts keep 4x32B loads in flight.
// 512 blocks, __launch_bounds__(256,4) -> >=4 blocks/SM -> single wave.

struct F8 { float f[8]; };

__device__ __forceinline__ F8 ldg256_ef(const float* p)
{
    F8 r;
    asm("ld.global.nc.L2::evict_first.v8.b32 {%0,%1,%2,%3,%4,%5,%6,%7}, [%8];"
        : "=f"(r.f[0]), "=f"(r.f[1]), "=f"(r.f[2]), "=f"(r.f[3]),
          "=f"(r.f[4]), "=f"(r.f[5]), "=f"(r.f[6]), "=f"(r.f[7])
        : "l"(p));
    return r;
}

__device__ __forceinline__ void stg256_el(float* p, const F8& v)
{
    asm volatile("st.global.L2::evict_last.v8.b32 [%0], {%1,%2,%3,%4,%5,%6,%7,%8};"
                 :: "l"(p),
                    "f"(v.f[0]), "f"(v.f[1]), "f"(v.f[2]), "f"(v.f[3]),
                    "f"(v.f[4]), "f"(v.f[5]), "f"(v.f[6]), "f"(v.f[7])
                 : "memory");
}

__device__ __forceinline__ F8 if_step8(const F8& xv, F8& v)
{
    F8 s;
    #pragma unroll
    for (int k = 0; k < 8; ++k) {
        float h = xv.f[k] + v.f[k];
        s.f[k] = (h >= 1.0f) ? 1.0f : 0.0f;
        v.f[k] = (h >= 1.0f) ? 0.0f : h;
    }
    return s;
}

// T must be a multiple of 4 (T=32 here). N must be a multiple of 8.
__global__ __launch_bounds__(256, 4) void if_scan_w256(
    const float* __restrict__ x,    // [T, N]
    const float* __restrict__ v0,   // [N]
    float* __restrict__ out,        // [T, N]
    int n8, int T)
{
    int i = blockIdx.x * blockDim.x + threadIdx.x;
    if (i >= n8) return;

    long long base = (long long)i * 8;
    long long stride = (long long)n8 * 8;   // floats per timestep

    F8 v;
    #pragma unroll
    for (int k = 0; k < 8; ++k) v.f[k] = v0[base + k];

    const float* xp = x + base;
    float* op = out + base;

    for (int t = 0; t < T; t += 4) {
        // read burst: 4 independent 32B loads
        F8 b0 = ldg256_ef(xp);
        F8 b1 = ldg256_ef(xp + stride);
        F8 b2 = ldg256_ef(xp + 2 * stride);
        F8 b3 = ldg256_ef(xp + 3 * stride);
        xp += 4 * stride;

        // compute + write burst
        F8 s0 = if_step8(b0, v);
        F8 s1 = if_step8(b1, v);
        F8 s2 = if_step8(b2, v);
        F8 s3 = if_step8(b3, v);

        stg256_el(op, s0);
        stg256_el(op + stride, s1);
        stg256_el(op + 2 * stride, s2);
        stg256_el(op + 3 * stride, s3);
        op += 4 * stride;
    }
}

// Generic fallback (any shape): float4 path.
__device__ __forceinline__ float4 if_step4(float4 xv, float4& v)
{
    float h0 = xv.x + v.x, h1 = xv.y + v.y, h2 = xv.z + v.z, h3 = xv.w + v.w;
    float4 s;
    s.x = (h0 >= 1.0f) ? 1.0f : 0.0f;
    s.y = (h1 >= 1.0f) ? 1.0f : 0.0f;
    s.z = (h2 >= 1.0f) ? 1.0f : 0.0f;
    s.w = (h3 >= 1.0f) ? 1.0f : 0.0f;
    v.x = (h0 >= 1.0f) ? 0.0f : h0;
    v.y = (h1 >= 1.0f) ? 0.0f : h1;
    v.z = (h2 >= 1.0f) ? 0.0f : h2;
    v.w = (h3 >= 1.0f) ? 0.0f : h3;
    return s;
}

__global__ __launch_bounds__(256) void if_scan_plain(
    const float4* __restrict__ x,
    const float4* __restrict__ v0,
    float4* __restrict__ out,
    int n4, int T)
{
    int i = blockIdx.x * blockDim.x + threadIdx.x;
    if (i >= n4) return;

    float4 v = v0[i];
    const float4* xp = x + i;
    float4* op = out + i;

    for (int t = 0; t < T; ++t) {
        float4 xv = __ldcs(xp); xp += n4;
        float4 s = if_step4(xv, v);
        __stcs(op, s); op += n4;
    }
}

extern "C" void kernel_launch(void* const* d_in, const int* in_sizes, int n_in,
                              void* d_out, int out_size)
{
    const float* x_seq  = (const float*)d_in[0];   // [T, B, D]
    const float* v_init = (const float*)d_in[1];   // [B, D]

    int N = in_sizes[1];              // B * D
    int T = in_sizes[0] / N;          // timesteps

    if ((N & 7) == 0 && (T & 3) == 0) {
        int n8 = N / 8;
        int block = 256;
        int grid = (n8 + block - 1) / block;
        if_scan_w256<<<grid, block>>>(
            x_seq, v_init, (float*)d_out, n8, T);
    } else {
        int n4 = N / 4;
        int block = 256;
        int grid = (n4 + block - 1) / block;
        if_scan_plain<<<grid, block>>>(
            (const float4*)x_seq, (const float4*)v_init,
            (float4*)d_out, n4, T);
    }
}

// round 10
// speedup vs baseline: 1.1383x; 1.1383x over previous
#include <cuda_runtime.h>

// IF neuron multi-step scan, hard reset:
//   h_t = x_t + v_{t-1};  s_t = (h_t >= 1) ? 1 : 0;  v_t = s_t ? 0 : h_t
//
// R10 = R3's winning structure (batch-4 double-buffered prefetch, MLP=8,
// one float4 lane per thread, __ldcs/__stcs) with wave-quantization fix:
// block=128 + __launch_bounds__(128,10) caps regs at 51 (loop needs ~44)
// -> 10 blocks/SM -> capacity 1480 of 2048 blocks -> 1.38 waves (R3: 1.73)
// and higher steady residency (1280 vs 1024 thr/SM).

__device__ __forceinline__ float4 if_step(float4 xv, float4& v)
{
    float h0 = xv.x + v.x;
    float h1 = xv.y + v.y;
    float h2 = xv.z + v.z;
    float h3 = xv.w + v.w;

    float4 s;
    s.x = (h0 >= 1.0f) ? 1.0f : 0.0f;
    s.y = (h1 >= 1.0f) ? 1.0f : 0.0f;
    s.z = (h2 >= 1.0f) ? 1.0f : 0.0f;
    s.w = (h3 >= 1.0f) ? 1.0f : 0.0f;

    v.x = (h0 >= 1.0f) ? 0.0f : h0;
    v.y = (h1 >= 1.0f) ? 0.0f : h1;
    v.z = (h2 >= 1.0f) ? 0.0f : h2;
    v.w = (h3 >= 1.0f) ? 0.0f : h3;
    return s;
}

#define BLOCK 128

// T must be a multiple of 4 (T=32 here).
__global__ __launch_bounds__(BLOCK, 10) void if_scan_b4_128(
    const float4* __restrict__ x,   // [T, n4]
    const float4* __restrict__ v0,  // [n4]
    float4* __restrict__ out,       // [T, n4]
    int n4, int T)
{
    int i = blockIdx.x * BLOCK + threadIdx.x;
    if (i >= n4) return;

    float4 v = v0[i];
    const float4* xp = x + i;
    float4* op = out + i;

    long long stride = n4;

    // prologue: load batch 0
    float4 buf[4];
    #pragma unroll
    for (int k = 0; k < 4; ++k)
        buf[k] = __ldcs(xp + (long long)k * stride);
    xp += 4 * stride;

    for (int t = 4; t < T; t += 4) {
        // prefetch next batch (8 loads in flight per thread)
        float4 nxt[4];
        #pragma unroll
        for (int k = 0; k < 4; ++k)
            nxt[k] = __ldcs(xp + (long long)k * stride);
        xp += 4 * stride;

        // compute + store current batch (write burst)
        #pragma unroll
        for (int k = 0; k < 4; ++k) {
            float4 s = if_step(buf[k], v);
            __stcs(op, s);
            op += stride;
        }

        #pragma unroll
        for (int k = 0; k < 4; ++k) buf[k] = nxt[k];
    }

    // epilogue
    #pragma unroll
    for (int k = 0; k < 4; ++k) {
        float4 s = if_step(buf[k], v);
        __stcs(op, s);
        op += stride;
    }
}

// Generic fallback for T not divisible by 4 (not hit for this shape).
__global__ __launch_bounds__(BLOCK) void if_scan_plain(
    const float4* __restrict__ x,
    const float4* __restrict__ v0,
    float4* __restrict__ out,
    int n4, int T)
{
    int i = blockIdx.x * BLOCK + threadIdx.x;
    if (i >= n4) return;

    float4 v = v0[i];
    const float4* xp = x + i;
    float4* op = out + i;

    for (int t = 0; t < T; ++t) {
        float4 xv = __ldcs(xp); xp += n4;
        float4 s = if_step(xv, v);
        __stcs(op, s); op += n4;
    }
}

extern "C" void kernel_launch(void* const* d_in, const int* in_sizes, int n_in,
                              void* d_out, int out_size)
{
    const float* x_seq  = (const float*)d_in[0];   // [T, B, D]
    const float* v_init = (const float*)d_in[1];   // [B, D]

    int N = in_sizes[1];              // B * D
    int T = in_sizes[0] / N;          // timesteps
    int n4 = N / 4;

    int grid = (n4 + BLOCK - 1) / BLOCK;

    if ((T & 3) == 0) {
        if_scan_b4_128<<<grid, BLOCK>>>(
            (const float4*)x_seq, (const float4*)v_init,
            (float4*)d_out, n4, T);
    } else {
        if_scan_plain<<<grid, BLOCK>>>(
            (const float4*)x_seq, (const float4*)v_init,
            (float4*)d_out, n4, T);
    }
}